// round 10
// baseline (speedup 1.0000x reference)
#include <cuda_runtime.h>
#include <cuda_bf16.h>
#include <math.h>

// Problem constants (shapes fixed by the reference)
#define MAXN 50000
#define MAXE 600000
#define FDIM 128
#define GMAX 64
#define CDIM 2

// ---------------------------------------------------------------------------
// Scratch (static __device__ — no allocation allowed)
// ---------------------------------------------------------------------------
__device__ int   g_cnt [MAXN];          // in-degree; consumed as cursor by scatter
__device__ int   g_off [MAXN + 1];      // CSR offsets
__device__ int   g_bsum[256];           // per-block sums for scan
__device__ int   g_csr [MAXE];          // CSR src lists (grouped by dst)
__device__ float g_dinv[MAXN];
__device__ float g_Hs  [MAXN * FDIM];   // (A@W) * dinv[row]
__device__ float g_O   [MAXN * FDIM];   // aggregated layer output
__device__ float g_pool[GMAX * FDIM];

// ---------------------------------------------------------------------------
// Helpers
// ---------------------------------------------------------------------------
__device__ __forceinline__ void atomicMaxFloat(float* a, float v) {
    if (v >= 0.f) atomicMax((int*)a, __float_as_int(v));
    else          atomicMin((unsigned int*)a, __float_as_uint(v));
}

// ---------------------------------------------------------------------------
// K1: init counters + pool buffer
// ---------------------------------------------------------------------------
__global__ void init_kernel(int n, int gtot) {
    int i = blockIdx.x * blockDim.x + threadIdx.x;
    if (i < n) g_cnt[i] = 0;
    if (i < gtot) g_pool[i] = -3.402823466e38f;
}

// K2: in-degree histogram
__global__ void count_kernel(const int* __restrict__ dst, int E) {
    int e = blockIdx.x * blockDim.x + threadIdx.x;
    if (e < E) atomicAdd(&g_cnt[dst[e]], 1);
}

// K3a: per-block sums of g_cnt (256 elems per block, coalesced)
__global__ void bsum_kernel(int n) {
    int i = blockIdx.x * 256 + threadIdx.x;
    int v = (i < n) ? g_cnt[i] : 0;
#pragma unroll
    for (int o = 16; o; o >>= 1) v += __shfl_down_sync(0xffffffffu, v, o);
    __shared__ int ws[8];
    if ((threadIdx.x & 31) == 0) ws[threadIdx.x >> 5] = v;
    __syncthreads();
    if (threadIdx.x < 8) {
        int s = ws[threadIdx.x];
#pragma unroll
        for (int o = 4; o; o >>= 1) s += __shfl_down_sync(0xffu, s, o);
        if (threadIdx.x == 0) g_bsum[blockIdx.x] = s;
    }
}

// K3b: single-block exclusive scan of nb (<=256) block sums
__global__ void bscan_kernel(int nb) {
    int t = threadIdx.x;
    int v = (t < nb) ? g_bsum[t] : 0;
    int lane = t & 31, w = t >> 5;
    int x = v;
#pragma unroll
    for (int o = 1; o < 32; o <<= 1) {
        int y = __shfl_up_sync(0xffffffffu, x, o);
        if (lane >= o) x += y;
    }
    __shared__ int ws[8];
    if (lane == 31) ws[w] = x;
    __syncthreads();
    if (t < 8) {
        int s = ws[t];
#pragma unroll
        for (int o = 1; o < 8; o <<= 1) {
            int y = __shfl_up_sync(0xffu, s, o);
            if (t >= o) s += y;
        }
        ws[t] = s;
    }
    __syncthreads();
    int incl = x + (w ? ws[w - 1] : 0);
    if (t < nb) g_bsum[t] = incl - v;   // exclusive prefix
}

// K3c: per-block exclusive scan + global base -> g_off, plus dinv
__global__ void fill_kernel(int n) {
    int i = blockIdx.x * 256 + threadIdx.x;
    int c = (i < n) ? g_cnt[i] : 0;
    int lane = threadIdx.x & 31, w = threadIdx.x >> 5;
    int x = c;
#pragma unroll
    for (int o = 1; o < 32; o <<= 1) {
        int y = __shfl_up_sync(0xffffffffu, x, o);
        if (lane >= o) x += y;
    }
    __shared__ int ws[8];
    if (lane == 31) ws[w] = x;
    __syncthreads();
    if (threadIdx.x < 8) {
        int s = ws[threadIdx.x];
#pragma unroll
        for (int o = 1; o < 8; o <<= 1) {
            int y = __shfl_up_sync(0xffu, s, o);
            if (threadIdx.x >= o) s += y;
        }
        ws[threadIdx.x] = s;
    }
    __syncthreads();
    int excl = x - c + (w ? ws[w - 1] : 0);
    int off = g_bsum[blockIdx.x] + excl;
    if (i < n) {
        g_off[i]  = off;
        g_dinv[i] = rsqrtf((float)(c + 1));   // + self loop
        if (i == n - 1) g_off[n] = off + c;
    }
}

// K4: CSR fill (g_cnt doubles as countdown cursor; destroyed here)
__global__ void scatter_kernel(const int* __restrict__ src,
                               const int* __restrict__ dst, int E) {
    int e = blockIdx.x * blockDim.x + threadIdx.x;
    if (e >= E) return;
    int d = dst[e];
    int pos = atomicAdd(&g_cnt[d], -1) - 1;   // 0..deg-1 in reverse
    g_csr[g_off[d] + pos] = src[e];
}

// ---------------------------------------------------------------------------
// K5/K7: SGEMM  Hs = act(A) @ W * dinv[row]   [M x 128] x [128 x 128]
// 128x128 tile, BK=32, 256 threads, 8x8 micro-tile, conflict-free LDS.128.
// ---------------------------------------------------------------------------
template<bool RELU_A>
__global__ __launch_bounds__(256, 2)
void gemm_gcn(const float* __restrict__ A, const float* __restrict__ W,
              float* __restrict__ Hout, int M)
{
    const int BK = 32;
    __shared__ float As_T[BK][132];   // [k][m], pad 4
    __shared__ float Bs[BK][128];     // [k][n]

    int block_row = blockIdx.x * 128;
    int tid  = threadIdx.x;
    int wid  = tid >> 5;
    int lane = tid & 31;
    int warpRow = wid >> 2;           // 0..1  -> 64 rows
    int warpCol = wid & 3;            // 0..3  -> 32 cols
    int r = lane & 7;                 // 0..7
    int c = lane >> 3;                // 0..3
    int rowb = warpRow * 64 + r * 4;  // thread rows: rowb..+3, rowb+32..+35
    int colb = warpCol * 32 + c * 8;  // thread cols: colb..+7

    float acc[8][8];
#pragma unroll
    for (int i = 0; i < 8; i++)
#pragma unroll
        for (int j = 0; j < 8; j++) acc[i][j] = 0.f;

#pragma unroll
    for (int k0 = 0; k0 < 128; k0 += BK) {
#pragma unroll
        for (int i = 0; i < 4; i++) {
            int s  = tid + i * 256;     // 0..1023
            int m  = s >> 3;            // 0..127
            int kk = (s & 7) * 4;       // 0..28
            int gr = block_row + m;
            float4 v = make_float4(0.f, 0.f, 0.f, 0.f);
            if (gr < M) v = *(const float4*)(A + (size_t)gr * FDIM + k0 + kk);
            if (RELU_A) {
                v.x = fmaxf(v.x, 0.f); v.y = fmaxf(v.y, 0.f);
                v.z = fmaxf(v.z, 0.f); v.w = fmaxf(v.w, 0.f);
            }
            As_T[kk + 0][m] = v.x;
            As_T[kk + 1][m] = v.y;
            As_T[kk + 2][m] = v.z;
            As_T[kk + 3][m] = v.w;
        }
#pragma unroll
        for (int i = 0; i < 4; i++) {
            int s  = tid + i * 256;
            int kk = s >> 5;            // 0..31
            int n4 = (s & 31) * 4;      // 0..124
            *(float4*)&Bs[kk][n4] = *(const float4*)(W + (size_t)(k0 + kk) * FDIM + n4);
        }
        __syncthreads();

#pragma unroll
        for (int k = 0; k < BK; k++) {
            float4 a0 = *(float4*)&As_T[k][rowb];
            float4 a1 = *(float4*)&As_T[k][rowb + 32];
            float4 b0 = *(float4*)&Bs[k][colb];
            float4 b1 = *(float4*)&Bs[k][colb + 4];
            float a[8] = {a0.x, a0.y, a0.z, a0.w, a1.x, a1.y, a1.z, a1.w};
            float b[8] = {b0.x, b0.y, b0.z, b0.w, b1.x, b1.y, b1.z, b1.w};
#pragma unroll
            for (int i = 0; i < 8; i++)
#pragma unroll
                for (int j = 0; j < 8; j++) acc[i][j] += a[i] * b[j];
        }
        __syncthreads();
    }

    // epilogue: Hs = acc * dinv[row]
#pragma unroll
    for (int i = 0; i < 8; i++) {
        int gr = block_row + rowb + (i < 4 ? i : 28 + i);  // i>=4 -> +32+(i-4)
        if (gr >= M) continue;
        float dv = g_dinv[gr];
        float4 o0 = make_float4(acc[i][0] * dv, acc[i][1] * dv,
                                acc[i][2] * dv, acc[i][3] * dv);
        float4 o1 = make_float4(acc[i][4] * dv, acc[i][5] * dv,
                                acc[i][6] * dv, acc[i][7] * dv);
        *(float4*)(Hout + (size_t)gr * FDIM + colb)     = o0;
        *(float4*)(Hout + (size_t)gr * FDIM + colb + 4) = o1;
    }
}

// ---------------------------------------------------------------------------
// K6/K8: CSR gather aggregation, register-resident indices.
// FOUR warps per dst node; each warp owns a 32-float quarter of the row
// (lane = one float -> 128B coalesced per edge-row read).
// One coalesced load brings <=32 CSR indices into lane registers; shfl
// broadcasts feed the row loads, so row-load addresses never wait on memory.
// 8-way unrolled -> ~8 independent 128B loads in flight per warp.
//   O[d] = dinv[d] * (Hs[d] + sum_{s in N(d)} Hs[s]) + bias
// ---------------------------------------------------------------------------
__global__ __launch_bounds__(256)
void agg_kernel(const float* __restrict__ bias, int N)
{
    int gw   = (blockIdx.x * blockDim.x + threadIdx.x) >> 5;
    int node = gw >> 2;
    if (node >= N) return;
    int lane = threadIdx.x & 31;
    int col  = ((gw & 3) << 5) | lane;

    const float* __restrict__ H = g_Hs;
    float a0 = __ldg(&H[(size_t)node * FDIM + col]);   // self contribution
    float a1 = 0.f, a2 = 0.f, a3 = 0.f;
    float a4 = 0.f, a5 = 0.f, a6 = 0.f, a7 = 0.f;
    int beg = __ldg(&g_off[node]);
    int deg = __ldg(&g_off[node + 1]) - beg;

    for (int base = 0; base < deg; base += 32) {
        int m = deg - base; if (m > 32) m = 32;
        int idx = 0;
        if (lane < m) idx = __ldg(&g_csr[beg + base + lane]);
        int e = 0;
        for (; e + 8 <= m; e += 8) {
            int s0 = __shfl_sync(0xffffffffu, idx, e + 0);
            int s1 = __shfl_sync(0xffffffffu, idx, e + 1);
            int s2 = __shfl_sync(0xffffffffu, idx, e + 2);
            int s3 = __shfl_sync(0xffffffffu, idx, e + 3);
            int s4 = __shfl_sync(0xffffffffu, idx, e + 4);
            int s5 = __shfl_sync(0xffffffffu, idx, e + 5);
            int s6 = __shfl_sync(0xffffffffu, idx, e + 6);
            int s7 = __shfl_sync(0xffffffffu, idx, e + 7);
            a0 += __ldg(&H[(size_t)s0 * FDIM + col]);
            a1 += __ldg(&H[(size_t)s1 * FDIM + col]);
            a2 += __ldg(&H[(size_t)s2 * FDIM + col]);
            a3 += __ldg(&H[(size_t)s3 * FDIM + col]);
            a4 += __ldg(&H[(size_t)s4 * FDIM + col]);
            a5 += __ldg(&H[(size_t)s5 * FDIM + col]);
            a6 += __ldg(&H[(size_t)s6 * FDIM + col]);
            a7 += __ldg(&H[(size_t)s7 * FDIM + col]);
        }
        for (; e + 2 <= m; e += 2) {
            int s0 = __shfl_sync(0xffffffffu, idx, e + 0);
            int s1 = __shfl_sync(0xffffffffu, idx, e + 1);
            a0 += __ldg(&H[(size_t)s0 * FDIM + col]);
            a1 += __ldg(&H[(size_t)s1 * FDIM + col]);
        }
        for (; e < m; e++) {
            int s = __shfl_sync(0xffffffffu, idx, e);
            a0 += __ldg(&H[(size_t)s * FDIM + col]);
        }
    }
    float acc = ((a0 + a1) + (a2 + a3)) + ((a4 + a5) + (a6 + a7));
    g_O[(size_t)node * FDIM + col] = acc * g_dinv[node] + __ldg(&bias[col]);
}

// ---------------------------------------------------------------------------
// K9: segment max pool over sorted batch ids
// ---------------------------------------------------------------------------
#define POOL_NODES 256
__global__ void pool_kernel(const int* __restrict__ batch, int M)
{
    int j  = threadIdx.x;
    int n0 = blockIdx.x * POOL_NODES;
    int n1 = min(n0 + POOL_NODES, M);
    if (n0 >= M) return;
    int cur = __ldg(&batch[n0]);
    float m = -3.402823466e38f;
    for (int i = n0; i < n1; i++) {
        int b = __ldg(&batch[i]);
        if (b != cur) {
            atomicMaxFloat(&g_pool[cur * FDIM + j], m);
            cur = b;
            m = -3.402823466e38f;
        }
        m = fmaxf(m, g_O[(size_t)i * FDIM + j]);
    }
    atomicMaxFloat(&g_pool[cur * FDIM + j], m);
}

// ---------------------------------------------------------------------------
// K10: MLP head, one block per graph (128 threads)
// ---------------------------------------------------------------------------
__global__ void mlp_kernel(const float* __restrict__ Wl1, const float* __restrict__ bl1,
                           const float* __restrict__ Wl2, const float* __restrict__ bl2,
                           const float* __restrict__ Wo,  const float* __restrict__ bo,
                           float* __restrict__ out)
{
    __shared__ float gv[128], t1[128], t2[128], logits[CDIM];
    int g = blockIdx.x, j = threadIdx.x;

    gv[j] = g_pool[g * FDIM + j];
    __syncthreads();

    float acc = bl1[j];
#pragma unroll 8
    for (int k = 0; k < 128; k++) acc += gv[k] * Wl1[k * 128 + j];
    t1[j] = fmaxf(acc, 0.f);
    __syncthreads();

    acc = bl2[j];
#pragma unroll 8
    for (int k = 0; k < 128; k++) acc += t1[k] * Wl2[k * 128 + j];
    t2[j] = fmaxf(acc, 0.f);
    __syncthreads();

    if (j < CDIM) {
        float l = bo[j];
#pragma unroll 8
        for (int k = 0; k < 128; k++) l += t2[k] * Wo[k * CDIM + j];
        logits[j] = l;
    }
    __syncthreads();

    if (j < CDIM) {
        float m = fmaxf(logits[0], logits[1]);
        float e = expf(logits[j] - m);
        float s = expf(logits[0] - m) + expf(logits[1] - m);
        out[g * CDIM + j] = e / s;
    }
}

// ---------------------------------------------------------------------------
// Launch: 0:x 1:edge_index 2:batch 3:W1 4:b1 5:W2 6:b2 7:Wl1 8:bl1 9:Wl2
//         10:bl2 11:Wo 12:bo
// ---------------------------------------------------------------------------
extern "C" void kernel_launch(void* const* d_in, const int* in_sizes, int n_in,
                              void* d_out, int out_size)
{
    const float* x    = (const float*)d_in[0];
    const int*   ei   = (const int*)  d_in[1];
    const int*   batch= (const int*)  d_in[2];
    const float* W1   = (const float*)d_in[3];
    const float* b1   = (const float*)d_in[4];
    const float* W2   = (const float*)d_in[5];
    const float* b2   = (const float*)d_in[6];
    const float* Wl1  = (const float*)d_in[7];
    const float* bl1  = (const float*)d_in[8];
    const float* Wl2  = (const float*)d_in[9];
    const float* bl2  = (const float*)d_in[10];
    const float* Wo   = (const float*)d_in[11];
    const float* bo   = (const float*)d_in[12];
    float* out = (float*)d_out;

    int N = in_sizes[0] / FDIM;        // 50000
    int E = in_sizes[1] / 2;           // 600000
    int G = out_size / CDIM;           // 64
    const int* src = ei;               // edge_index[0]
    const int* dst = ei + E;           // edge_index[1]

    float *Hp, *Op;
    cudaGetSymbolAddress((void**)&Hp, g_Hs);
    cudaGetSymbolAddress((void**)&Op, g_O);

    // --- CSR build ---
    int initN = (N > G * FDIM) ? N : G * FDIM;
    int nb = (N + 255) / 256;          // 196 scan blocks
    init_kernel<<<(initN + 255) / 256, 256>>>(N, G * FDIM);
    count_kernel<<<(E + 255) / 256, 256>>>(dst, E);
    bsum_kernel<<<nb, 256>>>(N);
    bscan_kernel<<<1, 256>>>(nb);
    fill_kernel<<<nb, 256>>>(N);
    scatter_kernel<<<(E + 255) / 256, 256>>>(src, dst, E);

    int gemm_blocks = (N + 127) / 128;
    int agg_blocks  = (int)(((long long)N * 4 * 32 + 255) / 256);  // 4 warps/node

    // layer 1
    gemm_gcn<false><<<gemm_blocks, 256>>>(x, W1, Hp, N);
    agg_kernel<<<agg_blocks, 256>>>(b1, N);
    // layer 2 (relu fused into A-load)
    gemm_gcn<true><<<gemm_blocks, 256>>>(Op, W2, Hp, N);
    agg_kernel<<<agg_blocks, 256>>>(b2, N);

    pool_kernel<<<(N + POOL_NODES - 1) / POOL_NODES, 128>>>(batch, N);
    mlp_kernel<<<G, 128>>>(Wl1, bl1, Wl2, bl2, Wo, bo, out);
}

// round 14
// speedup vs baseline: 1.0825x; 1.0825x over previous
#include <cuda_runtime.h>
#include <cuda_bf16.h>
#include <math.h>
#include <stdint.h>

// Problem constants (shapes fixed by the reference)
#define MAXN 50000
#define FDIM 128
#define GMAX 64
#define CDIM 2

// ---------------------------------------------------------------------------
// Scratch (static __device__ — no allocation allowed)
// ---------------------------------------------------------------------------
__device__ float g_deg [MAXN];
__device__ float g_dinv[MAXN];
__device__ float g_Hs  [MAXN * FDIM];   // (A@W) * dinv[row]
__device__ float g_O   [MAXN * FDIM];   // layer-1 accumulation target / layer-2 input
__device__ float g_O2  [MAXN * FDIM];   // layer-2 accumulation target (no aliasing!)
__device__ float g_pool[GMAX * FDIM];

// ---------------------------------------------------------------------------
// Helpers
// ---------------------------------------------------------------------------
__device__ __forceinline__ void red_add_v4(float* addr, float4 v) {
    asm volatile("red.global.add.v4.f32 [%0], {%1,%2,%3,%4};"
                 :: "l"(addr), "f"(v.x), "f"(v.y), "f"(v.z), "f"(v.w) : "memory");
}

__device__ __forceinline__ void atomicMaxFloat(float* a, float v) {
    if (v >= 0.f) atomicMax((int*)a, __float_as_int(v));
    else          atomicMin((unsigned int*)a, __float_as_uint(v));
}

__device__ __forceinline__ void cp_async16(unsigned int smem_addr, const void* gptr, int src_bytes) {
    asm volatile("cp.async.cg.shared.global [%0], [%1], 16, %2;"
                 :: "r"(smem_addr), "l"(gptr), "r"(src_bytes));
}
__device__ __forceinline__ void cp_commit() {
    asm volatile("cp.async.commit_group;" ::);
}

// ---------------------------------------------------------------------------
// K1: init deg (=1 for self loop) + pool buffer
// ---------------------------------------------------------------------------
__global__ void init_kernel(int n, int gtot) {
    int i = blockIdx.x * blockDim.x + threadIdx.x;
    if (i < n) g_deg[i] = 1.0f;
    if (i < gtot) g_pool[i] = -3.402823466e38f;
}

// K2: in-degree over edges
__global__ void deg_kernel(const int* __restrict__ dst, int E) {
    int e = blockIdx.x * blockDim.x + threadIdx.x;
    if (e < E) atomicAdd(&g_deg[dst[e]], 1.0f);
}

// K3: dinv = rsqrt(deg)
__global__ void dinv_kernel(int n) {
    int i = blockIdx.x * blockDim.x + threadIdx.x;
    if (i < n) g_dinv[i] = rsqrtf(g_deg[i]);
}

// ---------------------------------------------------------------------------
// K4/K7: SGEMM  Hs = A @ W * dinv[row]   [M x 128] x [128 x 128]
// 128x64 block tile (grid.y = 2 col-halves), BK=16, 256 threads, double-
// buffered cp.async pipeline, 4x8 microtile, conflict-free LDS.
// Writes identical result to BOTH Hs and O (O is the atomic accumulation
// target seeded with the self-loop contribution). O must NOT alias A.
// ---------------------------------------------------------------------------
__global__ __launch_bounds__(256, 3)
void gemm_gcn(const float* __restrict__ A, const float* __restrict__ W,
              float* __restrict__ Hs, float* __restrict__ O, int M)
{
    __shared__ float As[2][128][20];   // [buf][m][k], pad 20
    __shared__ float Bs[2][16][68];    // [buf][k][n], pad 68

    const int tid  = threadIdx.x;
    const int wid  = tid >> 5;
    const int lane = tid & 31;
    const int block_row = blockIdx.x * 128;
    const int n_base    = blockIdx.y * 64;
    const int warpRow = wid >> 1;             // 0..3 -> 32 rows
    const int g       = lane >> 2;            // 0..7
    const int cb      = (wid & 1) * 32 + (lane & 3) * 8;  // 0..56

    unsigned int asBase = (unsigned int)__cvta_generic_to_shared(&As[0][0][0]);
    unsigned int bsBase = (unsigned int)__cvta_generic_to_shared(&Bs[0][0][0]);

    float acc[4][8];
#pragma unroll
    for (int i = 0; i < 4; i++)
#pragma unroll
        for (int j = 0; j < 8; j++) acc[i][j] = 0.f;

    auto issue = [&](int s) {
        int k0 = s * 16;
        int b  = s & 1;
        // A tile: 128 rows x 16 k = 512 float4 -> 2 per thread
#pragma unroll
        for (int j = 0; j < 2; j++) {
            int idx = tid + j * 256;           // 0..511
            int m   = idx >> 2;                // 0..127
            int kk  = (idx & 3) * 4;           // 0,4,8,12
            const float* srcp = A + (size_t)(block_row + m) * FDIM + k0 + kk;
            unsigned int dsta = asBase + (unsigned int)(((b * 128 + m) * 20 + kk) * 4);
            int sz = (block_row + m < M) ? 16 : 0;   // zero-fill OOB rows
            cp_async16(dsta, srcp, sz);
        }
        // B tile: 16 k x 64 n = 256 float4 -> 1 per thread
        {
            int kk = tid >> 4;                 // 0..15
            int n4 = (tid & 15) * 4;           // 0..60
            const float* srcp = W + (size_t)(k0 + kk) * FDIM + n_base + n4;
            unsigned int dsta = bsBase + (unsigned int)(((b * 16 + kk) * 68 + n4) * 4);
            cp_async16(dsta, srcp, 16);
        }
        cp_commit();
    };

    issue(0);
    issue(1);

#pragma unroll
    for (int it = 0; it < 8; it++) {
        if (it < 7) asm volatile("cp.async.wait_group 1;" ::);
        else        asm volatile("cp.async.wait_group 0;" ::);
        __syncthreads();

        int b = it & 1;
#pragma unroll
        for (int k = 0; k < 16; k++) {
            float4 b0 = *(float4*)&Bs[b][k][cb];
            float4 b1 = *(float4*)&Bs[b][k][cb + 4];
            float av[4];
#pragma unroll
            for (int i = 0; i < 4; i++)
                av[i] = As[b][warpRow * 32 + g + i * 8][k];
            float bv[8] = {b0.x, b0.y, b0.z, b0.w, b1.x, b1.y, b1.z, b1.w};
#pragma unroll
            for (int i = 0; i < 4; i++)
#pragma unroll
                for (int j = 0; j < 8; j++) acc[i][j] += av[i] * bv[j];
        }

        if (it < 6) {
            __syncthreads();
            issue(it + 2);
        }
    }

    // epilogue: scale by dinv[row], write to both Hs and O
#pragma unroll
    for (int i = 0; i < 4; i++) {
        int gr = block_row + warpRow * 32 + g + i * 8;
        if (gr >= M) continue;
        float dv = g_dinv[gr];
        float4 o0 = make_float4(acc[i][0] * dv, acc[i][1] * dv,
                                acc[i][2] * dv, acc[i][3] * dv);
        float4 o1 = make_float4(acc[i][4] * dv, acc[i][5] * dv,
                                acc[i][6] * dv, acc[i][7] * dv);
        size_t base = (size_t)gr * FDIM + n_base + cb;
        *(float4*)(Hs + base)     = o0;
        *(float4*)(Hs + base + 4) = o1;
        *(float4*)(O  + base)     = o0;
        *(float4*)(O  + base + 4) = o1;
    }
}

// ---------------------------------------------------------------------------
// K5/K8: edge aggregation. One warp per edge, PURE add (no norm math):
//   O[dst] += Hs[src]        via red.global.add.v4.f32
// ---------------------------------------------------------------------------
__global__ __launch_bounds__(256)
void agg_kernel(const int* __restrict__ src, const int* __restrict__ dst,
                float* __restrict__ O, int E)
{
    int e = (blockIdx.x * blockDim.x + threadIdx.x) >> 5;
    if (e >= E) return;
    int lane = threadIdx.x & 31;
    int s = __ldg(&src[e]);
    int d = __ldg(&dst[e]);
    float4 v = *(const float4*)(g_Hs + (size_t)s * FDIM + lane * 4);
    red_add_v4(O + (size_t)d * FDIM + lane * 4, v);
}

// ---------------------------------------------------------------------------
// K6: layer-1 finalize (in place):  O = relu(O * dinv[row] + b1[col])
// ---------------------------------------------------------------------------
__global__ void finalize_kernel(const float* __restrict__ bias, int N)
{
    int i = blockIdx.x * blockDim.x + threadIdx.x;   // one float4 per thread
    int row = i >> 5;
    if (row >= N) return;
    int c4 = (i & 31) * 4;
    float dv = g_dinv[row];
    float4 v = *(float4*)(g_O + (size_t)row * FDIM + c4);
    float4 b = *(const float4*)(bias + c4);
    v.x = fmaxf(v.x * dv + b.x, 0.f);
    v.y = fmaxf(v.y * dv + b.y, 0.f);
    v.z = fmaxf(v.z * dv + b.z, 0.f);
    v.w = fmaxf(v.w * dv + b.w, 0.f);
    *(float4*)(g_O + (size_t)row * FDIM + c4) = v;
}

// ---------------------------------------------------------------------------
// K9: segment max pool over sorted batch ids, with layer-2 finalize fused:
//   val = O2[i][j] * dinv[i] + b2[j]
// ---------------------------------------------------------------------------
#define POOL_NODES 256
__global__ void pool_kernel(const int* __restrict__ batch,
                            const float* __restrict__ bias, int M)
{
    int j  = threadIdx.x;
    int n0 = blockIdx.x * POOL_NODES;
    int n1 = min(n0 + POOL_NODES, M);
    if (n0 >= M) return;
    float bj = __ldg(&bias[j]);
    int cur = __ldg(&batch[n0]);
    float m = -3.402823466e38f;
    for (int i = n0; i < n1; i++) {
        int b = __ldg(&batch[i]);
        if (b != cur) {
            atomicMaxFloat(&g_pool[cur * FDIM + j], m);
            cur = b;
            m = -3.402823466e38f;
        }
        float v = g_O2[(size_t)i * FDIM + j] * g_dinv[i] + bj;
        m = fmaxf(m, v);
    }
    atomicMaxFloat(&g_pool[cur * FDIM + j], m);
}

// ---------------------------------------------------------------------------
// K10: MLP head, one block per graph (128 threads)
// ---------------------------------------------------------------------------
__global__ void mlp_kernel(const float* __restrict__ Wl1, const float* __restrict__ bl1,
                           const float* __restrict__ Wl2, const float* __restrict__ bl2,
                           const float* __restrict__ Wo,  const float* __restrict__ bo,
                           float* __restrict__ out)
{
    __shared__ float gv[128], t1[128], t2[128], logits[CDIM];
    int g = blockIdx.x, j = threadIdx.x;

    gv[j] = g_pool[g * FDIM + j];
    __syncthreads();

    float acc = bl1[j];
#pragma unroll 8
    for (int k = 0; k < 128; k++) acc += gv[k] * Wl1[k * 128 + j];
    t1[j] = fmaxf(acc, 0.f);
    __syncthreads();

    acc = bl2[j];
#pragma unroll 8
    for (int k = 0; k < 128; k++) acc += t1[k] * Wl2[k * 128 + j];
    t2[j] = fmaxf(acc, 0.f);
    __syncthreads();

    if (j < CDIM) {
        float l = bo[j];
#pragma unroll 8
        for (int k = 0; k < 128; k++) l += t2[k] * Wo[k * CDIM + j];
        logits[j] = l;
    }
    __syncthreads();

    if (j < CDIM) {
        float m = fmaxf(logits[0], logits[1]);
        float e = expf(logits[j] - m);
        float s = expf(logits[0] - m) + expf(logits[1] - m);
        out[g * CDIM + j] = e / s;
    }
}

// ---------------------------------------------------------------------------
// Launch: 0:x 1:edge_index 2:batch 3:W1 4:b1 5:W2 6:b2 7:Wl1 8:bl1 9:Wl2
//         10:bl2 11:Wo 12:bo
// ---------------------------------------------------------------------------
extern "C" void kernel_launch(void* const* d_in, const int* in_sizes, int n_in,
                              void* d_out, int out_size)
{
    const float* x    = (const float*)d_in[0];
    const int*   ei   = (const int*)  d_in[1];
    const int*   batch= (const int*)  d_in[2];
    const float* W1   = (const float*)d_in[3];
    const float* b1   = (const float*)d_in[4];
    const float* W2   = (const float*)d_in[5];
    const float* b2   = (const float*)d_in[6];
    const float* Wl1  = (const float*)d_in[7];
    const float* bl1  = (const float*)d_in[8];
    const float* Wl2  = (const float*)d_in[9];
    const float* bl2  = (const float*)d_in[10];
    const float* Wo   = (const float*)d_in[11];
    const float* bo   = (const float*)d_in[12];
    float* out = (float*)d_out;

    int N = in_sizes[0] / FDIM;        // 50000
    int E = in_sizes[1] / 2;           // 600000
    int G = out_size / CDIM;           // 64
    const int* src = ei;               // edge_index[0]
    const int* dst = ei + E;           // edge_index[1]

    float *Hp, *Op, *O2p;
    cudaGetSymbolAddress((void**)&Hp,  g_Hs);
    cudaGetSymbolAddress((void**)&Op,  g_O);
    cudaGetSymbolAddress((void**)&O2p, g_O2);

    int initN = (N > G * FDIM) ? N : G * FDIM;
    init_kernel<<<(initN + 255) / 256, 256>>>(N, G * FDIM);
    deg_kernel<<<(E + 255) / 256, 256>>>(dst, E);
    dinv_kernel<<<(N + 255) / 256, 256>>>(N);

    dim3 gemm_grid((N + 127) / 128, 2);
    int agg_blocks = (int)(((long long)E * 32 + 255) / 256);
    int fin_blocks = (int)(((long long)N * 32 + 255) / 256);

    // layer 1: Hs,O = (x@W1)*dinv ; O += Hs[src] ; O = relu(O*dinv + b1)
    gemm_gcn<<<gemm_grid, 256>>>(x, W1, Hp, Op, N);
    agg_kernel<<<agg_blocks, 256>>>(src, dst, Op, E);
    finalize_kernel<<<fin_blocks, 256>>>(b1, N);

    // layer 2: Hs,O2 = (O@W2)*dinv ; O2 += Hs[src] ; (×dinv + b2 fused in pool)
    gemm_gcn<<<gemm_grid, 256>>>(Op, W2, Hp, O2p, N);
    agg_kernel<<<agg_blocks, 256>>>(src, dst, O2p, E);

    pool_kernel<<<(N + POOL_NODES - 1) / POOL_NODES, 128>>>(batch, b2, N);
    mlp_kernel<<<G, 128>>>(Wl1, bl1, Wl2, bl2, Wo, bo, out);
}

// round 15
// speedup vs baseline: 1.1845x; 1.0942x over previous
#include <cuda_runtime.h>
#include <cuda_bf16.h>
#include <math.h>
#include <stdint.h>

// Problem constants (shapes fixed by the reference)
#define MAXN 50000
#define FDIM 128
#define GMAX 64
#define CDIM 2

// smem layout for gemm_tc (floats)
#define SA_STRIDE 132
#define W_STRIDE  136
#define SA_OFF    0
#define WH_OFF    (128 * SA_STRIDE)                 // 16896
#define WL_OFF    (WH_OFF + 128 * W_STRIDE)         // 34304
#define SMEM_FLOATS (WL_OFF + 128 * W_STRIDE)       // 51712
#define SMEM_BYTES  (SMEM_FLOATS * 4)               // 206848

// ---------------------------------------------------------------------------
// Scratch (static __device__ — no allocation allowed)
// ---------------------------------------------------------------------------
__device__ float g_deg [MAXN];
__device__ float g_dinv[MAXN];
__device__ float g_Hs  [MAXN * FDIM];   // (A@W) * dinv[row]  (edge-gather source)
__device__ float g_O   [MAXN * FDIM];   // accumulation target / layer input
__device__ float g_pool[GMAX * FDIM];

// ---------------------------------------------------------------------------
// Helpers
// ---------------------------------------------------------------------------
__device__ __forceinline__ void red_add_v4(float* addr, float4 v) {
    asm volatile("red.global.add.v4.f32 [%0], {%1,%2,%3,%4};"
                 :: "l"(addr), "f"(v.x), "f"(v.y), "f"(v.z), "f"(v.w) : "memory");
}

__device__ __forceinline__ void atomicMaxFloat(float* a, float v) {
    if (v >= 0.f) atomicMax((int*)a, __float_as_int(v));
    else          atomicMin((unsigned int*)a, __float_as_uint(v));
}

__device__ __forceinline__ unsigned f2tf32(float x) {
    unsigned r;
    asm("cvt.rna.tf32.f32 %0, %1;" : "=r"(r) : "f"(x));
    return r;
}

__device__ __forceinline__ void mma_tf32(float d[4], const unsigned a[4], const unsigned b[2]) {
    asm volatile("mma.sync.aligned.m16n8k8.row.col.f32.tf32.tf32.f32 "
                 "{%0,%1,%2,%3}, {%4,%5,%6,%7}, {%8,%9}, {%0,%1,%2,%3};"
                 : "+f"(d[0]), "+f"(d[1]), "+f"(d[2]), "+f"(d[3])
                 : "r"(a[0]), "r"(a[1]), "r"(a[2]), "r"(a[3]),
                   "r"(b[0]), "r"(b[1]));
}

// ---------------------------------------------------------------------------
// K1: init deg (=1 for self loop) + pool buffer
// ---------------------------------------------------------------------------
__global__ void init_kernel(int n, int gtot) {
    int i = blockIdx.x * blockDim.x + threadIdx.x;
    if (i < n) g_deg[i] = 1.0f;
    if (i < gtot) g_pool[i] = -3.402823466e38f;
}

// K2: in-degree over edges
__global__ void deg_kernel(const int* __restrict__ dst, int E) {
    int e = blockIdx.x * blockDim.x + threadIdx.x;
    if (e < E) atomicAdd(&g_deg[dst[e]], 1.0f);
}

// K3: dinv = rsqrt(deg)
__global__ void dinv_kernel(int n) {
    int i = blockIdx.x * blockDim.x + threadIdx.x;
    if (i < n) g_dinv[i] = rsqrtf(g_deg[i]);
}

// ---------------------------------------------------------------------------
// K4/K7: tensor-core GEMM (tf32 x3 split, fp32-class accuracy)
//   Hs = (A @ W) * dinv[row] ; O = same (seed for the atomic aggregation)
// One CTA per 128 rows, full K=128 in smem. 8 warps = 2(M) x 4(N);
// warp tile 64x32 = 4x4 m16n8k8 tiles. W hi/lo precomputed once in smem.
// In-place safe for layer 2 (O==A): all A reads happen before epilogue.
// ---------------------------------------------------------------------------
__global__ __launch_bounds__(256)
void gemm_tc(const float* __restrict__ A, const float* __restrict__ W,
             float* __restrict__ Hs, float* __restrict__ O, int M)
{
    extern __shared__ float sm[];
    float* SA = sm + SA_OFF;
    float* WH = sm + WH_OFF;
    float* WL = sm + WL_OFF;

    const int tid  = threadIdx.x;
    const int wid  = tid >> 5;
    const int lane = tid & 31;
    const int g = lane >> 2;          // 0..7
    const int t = lane & 3;           // 0..3
    const int warpM = wid & 1;        // 0..1 -> 64 rows
    const int warpN = wid >> 1;       // 0..3 -> 32 cols
    const int blockRow = blockIdx.x * 128;

    // --- W -> tf32 hi/lo in smem (coalesced) ---
    for (int i = tid; i < 16384; i += 256) {
        int k = i >> 7, n = i & 127;
        float w = W[i];
        unsigned hi = f2tf32(w);
        float lof = w - __uint_as_float(hi);
        unsigned lo = f2tf32(lof);
        WH[k * W_STRIDE + n] = __uint_as_float(hi);
        WL[k * W_STRIDE + n] = __uint_as_float(lo);
    }

    // --- A tile (128 x 128), zero-fill OOB rows ---
#pragma unroll
    for (int i = 0; i < 16; i++) {
        int s  = tid + i * 256;       // 0..4095 float4 slots
        int m  = s >> 5;              // 0..127
        int k4 = (s & 31) * 4;        // 0..124
        int row = blockRow + m;
        float4 v = make_float4(0.f, 0.f, 0.f, 0.f);
        if (row < M) v = *(const float4*)(A + (size_t)row * FDIM + k4);
        *(float4*)&SA[m * SA_STRIDE + k4] = v;
    }
    __syncthreads();

    float d[4][4][4];
#pragma unroll
    for (int mt = 0; mt < 4; mt++)
#pragma unroll
        for (int nt = 0; nt < 4; nt++)
#pragma unroll
            for (int q = 0; q < 4; q++) d[mt][nt][q] = 0.f;

#pragma unroll 2
    for (int ks = 0; ks < 16; ks++) {
        int k0 = ks * 8;

        unsigned ah[4][4], al[4][4];
#pragma unroll
        for (int mt = 0; mt < 4; mt++) {
            int rb = warpM * 64 + mt * 16;
            float f0 = SA[(rb + g)     * SA_STRIDE + k0 + t];
            float f1 = SA[(rb + g + 8) * SA_STRIDE + k0 + t];
            float f2 = SA[(rb + g)     * SA_STRIDE + k0 + t + 4];
            float f3 = SA[(rb + g + 8) * SA_STRIDE + k0 + t + 4];
            ah[mt][0] = f2tf32(f0); al[mt][0] = f2tf32(f0 - __uint_as_float(ah[mt][0]));
            ah[mt][1] = f2tf32(f1); al[mt][1] = f2tf32(f1 - __uint_as_float(ah[mt][1]));
            ah[mt][2] = f2tf32(f2); al[mt][2] = f2tf32(f2 - __uint_as_float(ah[mt][2]));
            ah[mt][3] = f2tf32(f3); al[mt][3] = f2tf32(f3 - __uint_as_float(ah[mt][3]));
        }

        unsigned bh[4][2], bl[4][2];
#pragma unroll
        for (int nt = 0; nt < 4; nt++) {
            int c0 = warpN * 32 + nt * 8 + g;
            bh[nt][0] = __float_as_uint(WH[(k0 + t)     * W_STRIDE + c0]);
            bh[nt][1] = __float_as_uint(WH[(k0 + t + 4) * W_STRIDE + c0]);
            bl[nt][0] = __float_as_uint(WL[(k0 + t)     * W_STRIDE + c0]);
            bl[nt][1] = __float_as_uint(WL[(k0 + t + 4) * W_STRIDE + c0]);
        }

#pragma unroll
        for (int mt = 0; mt < 4; mt++)
#pragma unroll
            for (int nt = 0; nt < 4; nt++) {
                mma_tf32(d[mt][nt], ah[mt], bh[nt]);
                mma_tf32(d[mt][nt], ah[mt], bl[nt]);
                mma_tf32(d[mt][nt], al[mt], bh[nt]);
            }
    }

    // --- epilogue: scale by dinv[row], write Hs and O ---
#pragma unroll
    for (int mt = 0; mt < 4; mt++) {
        int rbase = blockRow + warpM * 64 + mt * 16 + g;
#pragma unroll
        for (int half = 0; half < 2; half++) {
            int row = rbase + half * 8;
            if (row >= M) continue;
            float dv = g_dinv[row];
#pragma unroll
            for (int nt = 0; nt < 4; nt++) {
                float2 v;
                v.x = d[mt][nt][half * 2 + 0] * dv;
                v.y = d[mt][nt][half * 2 + 1] * dv;
                size_t off = (size_t)row * FDIM + warpN * 32 + nt * 8 + 2 * t;
                *(float2*)(Hs + off) = v;
                *(float2*)(O  + off) = v;
            }
        }
    }
}

// ---------------------------------------------------------------------------
// K5/K8: edge aggregation. One warp per edge, pure add:
//   O[dst] += Hs[src]        via red.global.add.v4.f32
// ---------------------------------------------------------------------------
__global__ __launch_bounds__(256)
void agg_kernel(const int* __restrict__ src, const int* __restrict__ dst, int E)
{
    int e = (blockIdx.x * blockDim.x + threadIdx.x) >> 5;
    if (e >= E) return;
    int lane = threadIdx.x & 31;
    int s = __ldg(&src[e]);
    int d = __ldg(&dst[e]);
    float4 v = *(const float4*)(g_Hs + (size_t)s * FDIM + lane * 4);
    red_add_v4(g_O + (size_t)d * FDIM + lane * 4, v);
}

// ---------------------------------------------------------------------------
// K6: layer-1 finalize (in place):  O = relu(O * dinv[row] + b1[col])
// ---------------------------------------------------------------------------
__global__ void finalize_kernel(const float* __restrict__ bias, int N)
{
    int i = blockIdx.x * blockDim.x + threadIdx.x;   // one float4 per thread
    int row = i >> 5;
    if (row >= N) return;
    int c4 = (i & 31) * 4;
    float dv = g_dinv[row];
    float4 v = *(float4*)(g_O + (size_t)row * FDIM + c4);
    float4 b = *(const float4*)(bias + c4);
    v.x = fmaxf(v.x * dv + b.x, 0.f);
    v.y = fmaxf(v.y * dv + b.y, 0.f);
    v.z = fmaxf(v.z * dv + b.z, 0.f);
    v.w = fmaxf(v.w * dv + b.w, 0.f);
    *(float4*)(g_O + (size_t)row * FDIM + c4) = v;
}

// ---------------------------------------------------------------------------
// K9: segment max pool over sorted batch ids, layer-2 finalize fused:
//   val = O[i][j] * dinv[i] + b2[j]
// ---------------------------------------------------------------------------
#define POOL_NODES 256
__global__ void pool_kernel(const int* __restrict__ batch,
                            const float* __restrict__ bias, int M)
{
    int j  = threadIdx.x;
    int n0 = blockIdx.x * POOL_NODES;
    int n1 = min(n0 + POOL_NODES, M);
    if (n0 >= M) return;
    float bj = __ldg(&bias[j]);
    int cur = __ldg(&batch[n0]);
    float m = -3.402823466e38f;
    for (int i = n0; i < n1; i++) {
        int b = __ldg(&batch[i]);
        if (b != cur) {
            atomicMaxFloat(&g_pool[cur * FDIM + j], m);
            cur = b;
            m = -3.402823466e38f;
        }
        float v = g_O[(size_t)i * FDIM + j] * g_dinv[i] + bj;
        m = fmaxf(m, v);
    }
    atomicMaxFloat(&g_pool[cur * FDIM + j], m);
}

// ---------------------------------------------------------------------------
// K10: MLP head, one block per graph (128 threads)
// ---------------------------------------------------------------------------
__global__ void mlp_kernel(const float* __restrict__ Wl1, const float* __restrict__ bl1,
                           const float* __restrict__ Wl2, const float* __restrict__ bl2,
                           const float* __restrict__ Wo,  const float* __restrict__ bo,
                           float* __restrict__ out)
{
    __shared__ float gv[128], t1[128], t2[128], logits[CDIM];
    int g = blockIdx.x, j = threadIdx.x;

    gv[j] = g_pool[g * FDIM + j];
    __syncthreads();

    float acc = bl1[j];
#pragma unroll 8
    for (int k = 0; k < 128; k++) acc += gv[k] * Wl1[k * 128 + j];
    t1[j] = fmaxf(acc, 0.f);
    __syncthreads();

    acc = bl2[j];
#pragma unroll 8
    for (int k = 0; k < 128; k++) acc += t1[k] * Wl2[k * 128 + j];
    t2[j] = fmaxf(acc, 0.f);
    __syncthreads();

    if (j < CDIM) {
        float l = bo[j];
#pragma unroll 8
        for (int k = 0; k < 128; k++) l += t2[k] * Wo[k * CDIM + j];
        logits[j] = l;
    }
    __syncthreads();

    if (j < CDIM) {
        float m = fmaxf(logits[0], logits[1]);
        float e = expf(logits[j] - m);
        float s = expf(logits[0] - m) + expf(logits[1] - m);
        out[g * CDIM + j] = e / s;
    }
}

// ---------------------------------------------------------------------------
// Launch: 0:x 1:edge_index 2:batch 3:W1 4:b1 5:W2 6:b2 7:Wl1 8:bl1 9:Wl2
//         10:bl2 11:Wo 12:bo
// ---------------------------------------------------------------------------
extern "C" void kernel_launch(void* const* d_in, const int* in_sizes, int n_in,
                              void* d_out, int out_size)
{
    const float* x    = (const float*)d_in[0];
    const int*   ei   = (const int*)  d_in[1];
    const int*   batch= (const int*)  d_in[2];
    const float* W1   = (const float*)d_in[3];
    const float* b1   = (const float*)d_in[4];
    const float* W2   = (const float*)d_in[5];
    const float* b2   = (const float*)d_in[6];
    const float* Wl1  = (const float*)d_in[7];
    const float* bl1  = (const float*)d_in[8];
    const float* Wl2  = (const float*)d_in[9];
    const float* bl2  = (const float*)d_in[10];
    const float* Wo   = (const float*)d_in[11];
    const float* bo   = (const float*)d_in[12];
    float* out = (float*)d_out;

    int N = in_sizes[0] / FDIM;        // 50000
    int E = in_sizes[1] / 2;           // 600000
    int G = out_size / CDIM;           // 64
    const int* src = ei;               // edge_index[0]
    const int* dst = ei + E;           // edge_index[1]

    float *Hp, *Op;
    cudaGetSymbolAddress((void**)&Hp, g_Hs);
    cudaGetSymbolAddress((void**)&Op, g_O);

    cudaFuncSetAttribute(gemm_tc, cudaFuncAttributeMaxDynamicSharedMemorySize,
                         SMEM_BYTES);

    int initN = (N > G * FDIM) ? N : G * FDIM;
    init_kernel<<<(initN + 255) / 256, 256>>>(N, G * FDIM);
    deg_kernel<<<(E + 255) / 256, 256>>>(dst, E);
    dinv_kernel<<<(N + 255) / 256, 256>>>(N);

    int gemm_blocks = (N + 127) / 128;
    int agg_blocks  = (int)(((long long)E * 32 + 255) / 256);
    int fin_blocks  = (int)(((long long)N * 32 + 255) / 256);

    // layer 1: Hs,O = (x@W1)*dinv ; O += Hs[src] ; O = relu(O*dinv + b1)
    gemm_tc<<<gemm_blocks, 256, SMEM_BYTES>>>(x, W1, Hp, Op, N);
    agg_kernel<<<agg_blocks, 256>>>(src, dst, E);
    finalize_kernel<<<fin_blocks, 256>>>(b1, N);

    // layer 2 (in place — block reads its rows before writing them):
    // Hs,O = (O@W2)*dinv ; O += Hs[src] ; (×dinv + b2 fused in pool)
    gemm_tc<<<gemm_blocks, 256, SMEM_BYTES>>>(Op, W2, Hp, Op, N);
    agg_kernel<<<agg_blocks, 256>>>(src, dst, E);

    pool_kernel<<<(N + POOL_NODES - 1) / POOL_NODES, 128>>>(batch, b2, N);
    mlp_kernel<<<G, 128>>>(Wl1, bl1, Wl2, bl2, Wo, bo, out);
}

// round 16
// speedup vs baseline: 1.3012x; 1.0985x over previous
#include <cuda_runtime.h>
#include <cuda_bf16.h>
#include <math.h>
#include <stdint.h>

// Problem constants (shapes fixed by the reference)
#define MAXN 50000
#define FDIM 128
#define GMAX 64
#define CDIM 2

#define SA_STRIDE 132
#define WFRAG_ELEMS 16384   // 16 ksteps * 16 colgroups * 32 lanes * 2

// ---------------------------------------------------------------------------
// Scratch (static __device__ — no allocation allowed)
// ---------------------------------------------------------------------------
__device__ float g_deg [MAXN];
__device__ float g_dinv[MAXN];
__device__ float g_Hs  [MAXN * FDIM];   // (A@W) * dinv[row]  (edge-gather source)
__device__ float g_O   [MAXN * FDIM];   // accumulation target / layer input
__device__ float g_pool[GMAX * FDIM];
__device__ float g_WHf [2][WFRAG_ELEMS]; // W hi, fragment-ordered, per layer
__device__ float g_WLf [2][WFRAG_ELEMS]; // W lo, fragment-ordered, per layer

// ---------------------------------------------------------------------------
// Helpers
// ---------------------------------------------------------------------------
__device__ __forceinline__ void red_add_v4(float* addr, float4 v) {
    asm volatile("red.global.add.v4.f32 [%0], {%1,%2,%3,%4};"
                 :: "l"(addr), "f"(v.x), "f"(v.y), "f"(v.z), "f"(v.w) : "memory");
}

__device__ __forceinline__ void atomicMaxFloat(float* a, float v) {
    if (v >= 0.f) atomicMax((int*)a, __float_as_int(v));
    else          atomicMin((unsigned int*)a, __float_as_uint(v));
}

__device__ __forceinline__ unsigned f2tf32(float x) {
    unsigned r;
    asm("cvt.rna.tf32.f32 %0, %1;" : "=r"(r) : "f"(x));
    return r;
}

__device__ __forceinline__ void mma_tf32(float d[4], const unsigned a[4], const unsigned b[2]) {
    asm volatile("mma.sync.aligned.m16n8k8.row.col.f32.tf32.tf32.f32 "
                 "{%0,%1,%2,%3}, {%4,%5,%6,%7}, {%8,%9}, {%0,%1,%2,%3};"
                 : "+f"(d[0]), "+f"(d[1]), "+f"(d[2]), "+f"(d[3])
                 : "r"(a[0]), "r"(a[1]), "r"(a[2]), "r"(a[3]),
                   "r"(b[0]), "r"(b[1]));
}

// ---------------------------------------------------------------------------
// K1: init deg (=1 for self loop) + pool buffer
// ---------------------------------------------------------------------------
__global__ void init_kernel(int n, int gtot) {
    int i = blockIdx.x * blockDim.x + threadIdx.x;
    if (i < n) g_deg[i] = 1.0f;
    if (i < gtot) g_pool[i] = -3.402823466e38f;
}

// K2: in-degree over edges
__global__ void deg_kernel(const int* __restrict__ dst, int E) {
    int e = blockIdx.x * blockDim.x + threadIdx.x;
    if (e < E) atomicAdd(&g_deg[dst[e]], 1.0f);
}

// K3: dinv = rsqrt(deg)
__global__ void dinv_kernel(int n) {
    int i = blockIdx.x * blockDim.x + threadIdx.x;
    if (i < n) g_dinv[i] = rsqrtf(g_deg[i]);
}

// ---------------------------------------------------------------------------
// K3b: W -> tf32 hi/lo in mma-fragment order.
// Fragment element (ks, ng, lane, h): k = ks*8 + (lane&3) + h*4,
//                                     n = ng*8 + (lane>>2)
// so a warp's b-fragment for (ks, ng) is one coalesced float2 per lane.
// ---------------------------------------------------------------------------
__global__ void wfrag_kernel(const float* __restrict__ W, int which) {
    int idx = blockIdx.x * 256 + threadIdx.x;
    if (idx >= WFRAG_ELEMS) return;
    int h    = idx & 1;
    int lane = (idx >> 1) & 31;
    int grp  = idx >> 6;            // ks*16 + ng
    int ks = grp >> 4, ng = grp & 15;
    int t = lane & 3, g = lane >> 2;
    int k = ks * 8 + t + h * 4;
    int n = ng * 8 + g;
    float w = W[k * FDIM + n];
    unsigned hi = f2tf32(w);
    float lof = w - __uint_as_float(hi);
    g_WHf[which][idx] = __uint_as_float(hi);
    g_WLf[which][idx] = __uint_as_float(f2tf32(lof));
}

// ---------------------------------------------------------------------------
// K4/K7: tensor-core GEMM (tf32 x3 split, fp32-class accuracy)
//   Hs = (A @ W) * dinv[row] ; O = same (seed for atomic aggregation)
// 64 rows per CTA (A tile in smem, 33.8KB), 8 warps = 2(M) x 4(N);
// warp tile 32x32 = 2x4 m16n8k8 tiles. W fragments from global (L2-resident).
// In-place safe for layer 2 (O==A): block reads its rows before writing.
// ---------------------------------------------------------------------------
__global__ __launch_bounds__(256, 3)
void gemm_tc(const float* __restrict__ A, int which,
             float* __restrict__ Hs, float* __restrict__ O, int M)
{
    __shared__ float SA[64 * SA_STRIDE];

    const int tid  = threadIdx.x;
    const int wid  = tid >> 5;
    const int lane = tid & 31;
    const int g = lane >> 2;          // 0..7
    const int t = lane & 3;           // 0..3
    const int warpM = wid & 1;        // 0..1 -> 32 rows
    const int warpN = wid >> 1;       // 0..3 -> 32 cols
    const int blockRow = blockIdx.x * 64;

    const float2* __restrict__ WHf = (const float2*)g_WHf[which];
    const float2* __restrict__ WLf = (const float2*)g_WLf[which];

    // --- A tile (64 x 128), zero-fill OOB rows: 2048 float4, 8 per thread ---
#pragma unroll
    for (int i = 0; i < 8; i++) {
        int s  = tid + i * 256;       // 0..2047
        int m  = s >> 5;              // 0..63
        int k4 = (s & 31) * 4;        // 0..124
        int row = blockRow + m;
        float4 v = make_float4(0.f, 0.f, 0.f, 0.f);
        if (row < M) v = *(const float4*)(A + (size_t)row * FDIM + k4);
        *(float4*)&SA[m * SA_STRIDE + k4] = v;
    }
    __syncthreads();

    float d[2][4][4];
#pragma unroll
    for (int mt = 0; mt < 2; mt++)
#pragma unroll
        for (int nt = 0; nt < 4; nt++)
#pragma unroll
            for (int q = 0; q < 4; q++) d[mt][nt][q] = 0.f;

#pragma unroll 2
    for (int ks = 0; ks < 16; ks++) {
        int k0 = ks * 8;

        unsigned ah[2][4], al[2][4];
#pragma unroll
        for (int mt = 0; mt < 2; mt++) {
            int rb = warpM * 32 + mt * 16;
            float f0 = SA[(rb + g)     * SA_STRIDE + k0 + t];
            float f1 = SA[(rb + g + 8) * SA_STRIDE + k0 + t];
            float f2 = SA[(rb + g)     * SA_STRIDE + k0 + t + 4];
            float f3 = SA[(rb + g + 8) * SA_STRIDE + k0 + t + 4];
            ah[mt][0] = f2tf32(f0); al[mt][0] = f2tf32(f0 - __uint_as_float(ah[mt][0]));
            ah[mt][1] = f2tf32(f1); al[mt][1] = f2tf32(f1 - __uint_as_float(ah[mt][1]));
            ah[mt][2] = f2tf32(f2); al[mt][2] = f2tf32(f2 - __uint_as_float(ah[mt][2]));
            ah[mt][3] = f2tf32(f3); al[mt][3] = f2tf32(f3 - __uint_as_float(ah[mt][3]));
        }

        unsigned bh[4][2], bl[4][2];
#pragma unroll
        for (int nt = 0; nt < 4; nt++) {
            int ng = warpN * 4 + nt;
            float2 vh = __ldg(&WHf[(ks * 16 + ng) * 32 + lane]);
            float2 vl = __ldg(&WLf[(ks * 16 + ng) * 32 + lane]);
            bh[nt][0] = __float_as_uint(vh.x); bh[nt][1] = __float_as_uint(vh.y);
            bl[nt][0] = __float_as_uint(vl.x); bl[nt][1] = __float_as_uint(vl.y);
        }

#pragma unroll
        for (int mt = 0; mt < 2; mt++)
#pragma unroll
            for (int nt = 0; nt < 4; nt++) {
                mma_tf32(d[mt][nt], ah[mt], bh[nt]);
                mma_tf32(d[mt][nt], ah[mt], bl[nt]);
                mma_tf32(d[mt][nt], al[mt], bh[nt]);
            }
    }

    // --- epilogue: scale by dinv[row], write Hs and O ---
#pragma unroll
    for (int mt = 0; mt < 2; mt++) {
        int rbase = blockRow + warpM * 32 + mt * 16 + g;
#pragma unroll
        for (int half = 0; half < 2; half++) {
            int row = rbase + half * 8;
            if (row >= M) continue;
            float dv = g_dinv[row];
#pragma unroll
            for (int nt = 0; nt < 4; nt++) {
                float2 v;
                v.x = d[mt][nt][half * 2 + 0] * dv;
                v.y = d[mt][nt][half * 2 + 1] * dv;
                size_t off = (size_t)row * FDIM + warpN * 32 + nt * 8 + 2 * t;
                *(float2*)(Hs + off) = v;
                *(float2*)(O  + off) = v;
            }
        }
    }
}

// ---------------------------------------------------------------------------
// K5/K8: edge aggregation. One warp per edge, pure add:
//   O[dst] += Hs[src]        via red.global.add.v4.f32
// ---------------------------------------------------------------------------
__global__ __launch_bounds__(256)
void agg_kernel(const int* __restrict__ src, const int* __restrict__ dst, int E)
{
    int e = (blockIdx.x * blockDim.x + threadIdx.x) >> 5;
    if (e >= E) return;
    int lane = threadIdx.x & 31;
    int s = __ldg(&src[e]);
    int d = __ldg(&dst[e]);
    float4 v = *(const float4*)(g_Hs + (size_t)s * FDIM + lane * 4);
    red_add_v4(g_O + (size_t)d * FDIM + lane * 4, v);
}

// ---------------------------------------------------------------------------
// K6: layer-1 finalize (in place):  O = relu(O * dinv[row] + b1[col])
// ---------------------------------------------------------------------------
__global__ void finalize_kernel(const float* __restrict__ bias, int N)
{
    int i = blockIdx.x * blockDim.x + threadIdx.x;   // one float4 per thread
    int row = i >> 5;
    if (row >= N) return;
    int c4 = (i & 31) * 4;
    float dv = g_dinv[row];
    float4 v = *(float4*)(g_O + (size_t)row * FDIM + c4);
    float4 b = *(const float4*)(bias + c4);
    v.x = fmaxf(v.x * dv + b.x, 0.f);
    v.y = fmaxf(v.y * dv + b.y, 0.f);
    v.z = fmaxf(v.z * dv + b.z, 0.f);
    v.w = fmaxf(v.w * dv + b.w, 0.f);
    *(float4*)(g_O + (size_t)row * FDIM + c4) = v;
}

// ---------------------------------------------------------------------------
// K9: segment max pool over sorted batch ids, layer-2 finalize fused:
//   val = O[i][j] * dinv[i] + b2[j]
// ---------------------------------------------------------------------------
#define POOL_NODES 256
__global__ void pool_kernel(const int* __restrict__ batch,
                            const float* __restrict__ bias, int M)
{
    int j  = threadIdx.x;
    int n0 = blockIdx.x * POOL_NODES;
    int n1 = min(n0 + POOL_NODES, M);
    if (n0 >= M) return;
    float bj = __ldg(&bias[j]);
    int cur = __ldg(&batch[n0]);
    float m = -3.402823466e38f;
    for (int i = n0; i < n1; i++) {
        int b = __ldg(&batch[i]);
        if (b != cur) {
            atomicMaxFloat(&g_pool[cur * FDIM + j], m);
            cur = b;
            m = -3.402823466e38f;
        }
        float v = g_O[(size_t)i * FDIM + j] * g_dinv[i] + bj;
        m = fmaxf(m, v);
    }
    atomicMaxFloat(&g_pool[cur * FDIM + j], m);
}

// ---------------------------------------------------------------------------
// K10: MLP head, one block per graph (128 threads)
// ---------------------------------------------------------------------------
__global__ void mlp_kernel(const float* __restrict__ Wl1, const float* __restrict__ bl1,
                           const float* __restrict__ Wl2, const float* __restrict__ bl2,
                           const float* __restrict__ Wo,  const float* __restrict__ bo,
                           float* __restrict__ out)
{
    __shared__ float gv[128], t1[128], t2[128], logits[CDIM];
    int g = blockIdx.x, j = threadIdx.x;

    gv[j] = g_pool[g * FDIM + j];
    __syncthreads();

    float acc = bl1[j];
#pragma unroll 8
    for (int k = 0; k < 128; k++) acc += gv[k] * Wl1[k * 128 + j];
    t1[j] = fmaxf(acc, 0.f);
    __syncthreads();

    acc = bl2[j];
#pragma unroll 8
    for (int k = 0; k < 128; k++) acc += t1[k] * Wl2[k * 128 + j];
    t2[j] = fmaxf(acc, 0.f);
    __syncthreads();

    if (j < CDIM) {
        float l = bo[j];
#pragma unroll 8
        for (int k = 0; k < 128; k++) l += t2[k] * Wo[k * CDIM + j];
        logits[j] = l;
    }
    __syncthreads();

    if (j < CDIM) {
        float m = fmaxf(logits[0], logits[1]);
        float e = expf(logits[j] - m);
        float s = expf(logits[0] - m) + expf(logits[1] - m);
        out[g * CDIM + j] = e / s;
    }
}

// ---------------------------------------------------------------------------
// Launch: 0:x 1:edge_index 2:batch 3:W1 4:b1 5:W2 6:b2 7:Wl1 8:bl1 9:Wl2
//         10:bl2 11:Wo 12:bo
// ---------------------------------------------------------------------------
extern "C" void kernel_launch(void* const* d_in, const int* in_sizes, int n_in,
                              void* d_out, int out_size)
{
    const float* x    = (const float*)d_in[0];
    const int*   ei   = (const int*)  d_in[1];
    const int*   batch= (const int*)  d_in[2];
    const float* W1   = (const float*)d_in[3];
    const float* b1   = (const float*)d_in[4];
    const float* W2   = (const float*)d_in[5];
    const float* b2   = (const float*)d_in[6];
    const float* Wl1  = (const float*)d_in[7];
    const float* bl1  = (const float*)d_in[8];
    const float* Wl2  = (const float*)d_in[9];
    const float* bl2  = (const float*)d_in[10];
    const float* Wo   = (const float*)d_in[11];
    const float* bo   = (const float*)d_in[12];
    float* out = (float*)d_out;

    int N = in_sizes[0] / FDIM;        // 50000
    int E = in_sizes[1] / 2;           // 600000
    int G = out_size / CDIM;           // 64
    const int* src = ei;               // edge_index[0]
    const int* dst = ei + E;           // edge_index[1]

    float *Hp, *Op;
    cudaGetSymbolAddress((void**)&Hp, g_Hs);
    cudaGetSymbolAddress((void**)&Op, g_O);

    int initN = (N > G * FDIM) ? N : G * FDIM;
    init_kernel<<<(initN + 255) / 256, 256>>>(N, G * FDIM);
    deg_kernel<<<(E + 255) / 256, 256>>>(dst, E);
    dinv_kernel<<<(N + 255) / 256, 256>>>(N);
    wfrag_kernel<<<(WFRAG_ELEMS + 255) / 256, 256>>>(W1, 0);
    wfrag_kernel<<<(WFRAG_ELEMS + 255) / 256, 256>>>(W2, 1);

    int gemm_blocks = (N + 63) / 64;
    int agg_blocks  = (int)(((long long)E * 32 + 255) / 256);
    int fin_blocks  = (int)(((long long)N * 32 + 255) / 256);

    // layer 1: Hs,O = (x@W1)*dinv ; O += Hs[src] ; O = relu(O*dinv + b1)
    gemm_tc<<<gemm_blocks, 256>>>(x, 0, Hp, Op, N);
    agg_kernel<<<agg_blocks, 256>>>(src, dst, E);
    finalize_kernel<<<fin_blocks, 256>>>(b1, N);

    // layer 2 (in place — block reads its rows before writing them):
    // Hs,O = (O@W2)*dinv ; O += Hs[src] ; (×dinv + b2 fused in pool)
    gemm_tc<<<gemm_blocks, 256>>>(Op, 1, Hp, Op, N);
    agg_kernel<<<agg_blocks, 256>>>(src, dst, E);

    pool_kernel<<<(N + POOL_NODES - 1) / POOL_NODES, 128>>>(batch, b2, N);
    mlp_kernel<<<G, 128>>>(Wl1, bl1, Wl2, bl2, Wo, bo, out);
}

// round 17
// speedup vs baseline: 1.3581x; 1.0437x over previous
#include <cuda_runtime.h>
#include <cuda_bf16.h>
#include <math.h>
#include <stdint.h>

// Problem constants (shapes fixed by the reference)
#define MAXN 50000
#define MAXE 600000
#define FDIM 128
#define GMAX 64
#define CDIM 2

#define SA_STRIDE 132
#define WFRAG_ELEMS 16384   // 16 ksteps * 16 colgroups * 32 lanes * 2

// ---------------------------------------------------------------------------
// Scratch (static __device__ — no allocation allowed)
// ---------------------------------------------------------------------------
__device__ float g_deg [MAXN];          // in-degree + 1 (dst-based, for dinv)
__device__ float g_dinv[MAXN];
__device__ int   g_cnt [MAXN];          // out-degree (src-based); scatter cursor
__device__ int   g_off [MAXN + 1];      // CSR-by-src offsets
__device__ int   g_bsum[256];
__device__ int   g_csr [MAXE];          // dst lists grouped by src
__device__ float g_Hs  [MAXN * FDIM];   // (A@W) * dinv[row]
__device__ float g_O   [MAXN * FDIM];   // accumulation target / layer input
__device__ float g_pool[GMAX * FDIM];
__device__ float g_WHf [2][WFRAG_ELEMS];
__device__ float g_WLf [2][WFRAG_ELEMS];

// ---------------------------------------------------------------------------
// Helpers
// ---------------------------------------------------------------------------
__device__ __forceinline__ void red_add_v4(float* addr, float4 v) {
    asm volatile("red.global.add.v4.f32 [%0], {%1,%2,%3,%4};"
                 :: "l"(addr), "f"(v.x), "f"(v.y), "f"(v.z), "f"(v.w) : "memory");
}

__device__ __forceinline__ void atomicMaxFloat(float* a, float v) {
    if (v >= 0.f) atomicMax((int*)a, __float_as_int(v));
    else          atomicMin((unsigned int*)a, __float_as_uint(v));
}

__device__ __forceinline__ unsigned f2tf32(float x) {
    unsigned r;
    asm("cvt.rna.tf32.f32 %0, %1;" : "=r"(r) : "f"(x));
    return r;
}

__device__ __forceinline__ void mma_tf32(float d[4], const unsigned a[4], const unsigned b[2]) {
    asm volatile("mma.sync.aligned.m16n8k8.row.col.f32.tf32.tf32.f32 "
                 "{%0,%1,%2,%3}, {%4,%5,%6,%7}, {%8,%9}, {%0,%1,%2,%3};"
                 : "+f"(d[0]), "+f"(d[1]), "+f"(d[2]), "+f"(d[3])
                 : "r"(a[0]), "r"(a[1]), "r"(a[2]), "r"(a[3]),
                   "r"(b[0]), "r"(b[1]));
}

// ---------------------------------------------------------------------------
// K1: init deg (=1 self loop), out-counts, pool
// ---------------------------------------------------------------------------
__global__ void init_kernel(int n, int gtot) {
    int i = blockIdx.x * blockDim.x + threadIdx.x;
    if (i < n) { g_deg[i] = 1.0f; g_cnt[i] = 0; }
    if (i < gtot) g_pool[i] = -3.402823466e38f;
}

// K2: one pass over edges: in-degree (dst) + out-degree (src)
__global__ void count_kernel(const int* __restrict__ src,
                             const int* __restrict__ dst, int E) {
    int e = blockIdx.x * blockDim.x + threadIdx.x;
    if (e >= E) return;
    atomicAdd(&g_deg[dst[e]], 1.0f);
    atomicAdd(&g_cnt[src[e]], 1);
}

// K3: per-block sums of g_cnt + dinv from g_deg (both ready after K2)
__global__ void bsum_dinv_kernel(int n) {
    int i = blockIdx.x * 256 + threadIdx.x;
    if (i < n) g_dinv[i] = rsqrtf(g_deg[i]);
    int v = (i < n) ? g_cnt[i] : 0;
#pragma unroll
    for (int o = 16; o; o >>= 1) v += __shfl_down_sync(0xffffffffu, v, o);
    __shared__ int ws[8];
    if ((threadIdx.x & 31) == 0) ws[threadIdx.x >> 5] = v;
    __syncthreads();
    if (threadIdx.x < 8) {
        int s = ws[threadIdx.x];
#pragma unroll
        for (int o = 4; o; o >>= 1) s += __shfl_down_sync(0xffu, s, o);
        if (threadIdx.x == 0) g_bsum[blockIdx.x] = s;
    }
}

// K4: single-block exclusive scan of nb (<=256) block sums
__global__ void bscan_kernel(int nb) {
    int t = threadIdx.x;
    int v = (t < nb) ? g_bsum[t] : 0;
    int lane = t & 31, w = t >> 5;
    int x = v;
#pragma unroll
    for (int o = 1; o < 32; o <<= 1) {
        int y = __shfl_up_sync(0xffffffffu, x, o);
        if (lane >= o) x += y;
    }
    __shared__ int ws[8];
    if (lane == 31) ws[w] = x;
    __syncthreads();
    if (t < 8) {
        int s = ws[t];
#pragma unroll
        for (int o = 1; o < 8; o <<= 1) {
            int y = __shfl_up_sync(0xffu, s, o);
            if (t >= o) s += y;
        }
        ws[t] = s;
    }
    __syncthreads();
    int incl = x + (w ? ws[w - 1] : 0);
    if (t < nb) g_bsum[t] = incl - v;
}

// K5: per-block exclusive scan + global base -> g_off
__global__ void fill_kernel(int n) {
    int i = blockIdx.x * 256 + threadIdx.x;
    int c = (i < n) ? g_cnt[i] : 0;
    int lane = threadIdx.x & 31, w = threadIdx.x >> 5;
    int x = c;
#pragma unroll
    for (int o = 1; o < 32; o <<= 1) {
        int y = __shfl_up_sync(0xffffffffu, x, o);
        if (lane >= o) x += y;
    }
    __shared__ int ws[8];
    if (lane == 31) ws[w] = x;
    __syncthreads();
    if (threadIdx.x < 8) {
        int s = ws[threadIdx.x];
#pragma unroll
        for (int o = 1; o < 8; o <<= 1) {
            int y = __shfl_up_sync(0xffu, s, o);
            if (threadIdx.x >= o) s += y;
        }
        ws[threadIdx.x] = s;
    }
    __syncthreads();
    int excl = x - c + (w ? ws[w - 1] : 0);
    int off = g_bsum[blockIdx.x] + excl;
    if (i < n) {
        g_off[i] = off;
        if (i == n - 1) g_off[n] = off + c;
    }
}

// K6: CSR fill (g_cnt consumed as countdown cursor)
__global__ void scatter_kernel(const int* __restrict__ src,
                               const int* __restrict__ dst, int E) {
    int e = blockIdx.x * blockDim.x + threadIdx.x;
    if (e >= E) return;
    int s = src[e];
    int pos = atomicAdd(&g_cnt[s], -1) - 1;
    g_csr[g_off[s] + pos] = dst[e];
}

// ---------------------------------------------------------------------------
// K7: W -> tf32 hi/lo in mma-fragment order, both layers in one launch
// ---------------------------------------------------------------------------
__global__ void wfrag_kernel(const float* __restrict__ W1,
                             const float* __restrict__ W2) {
    int which = blockIdx.y;
    const float* W = which ? W2 : W1;
    int idx = blockIdx.x * 256 + threadIdx.x;
    if (idx >= WFRAG_ELEMS) return;
    int h    = idx & 1;
    int lane = (idx >> 1) & 31;
    int grp  = idx >> 6;
    int ks = grp >> 4, ng = grp & 15;
    int t = lane & 3, g = lane >> 2;
    int k = ks * 8 + t + h * 4;
    int n = ng * 8 + g;
    float w = W[k * FDIM + n];
    unsigned hi = f2tf32(w);
    float lof = w - __uint_as_float(hi);
    g_WHf[which][idx] = __uint_as_float(hi);
    g_WLf[which][idx] = __uint_as_float(f2tf32(lof));
}

// ---------------------------------------------------------------------------
// K8/K10: tensor-core GEMM (tf32 x3), 64 rows/CTA, 3 CTAs/SM. Unchanged R16.
// ---------------------------------------------------------------------------
__global__ __launch_bounds__(256, 3)
void gemm_tc(const float* __restrict__ A, int which,
             float* __restrict__ Hs, float* __restrict__ O, int M)
{
    __shared__ float SA[64 * SA_STRIDE];

    const int tid  = threadIdx.x;
    const int wid  = tid >> 5;
    const int lane = tid & 31;
    const int g = lane >> 2;
    const int t = lane & 3;
    const int warpM = wid & 1;
    const int warpN = wid >> 1;
    const int blockRow = blockIdx.x * 64;

    const float2* __restrict__ WHf = (const float2*)g_WHf[which];
    const float2* __restrict__ WLf = (const float2*)g_WLf[which];

#pragma unroll
    for (int i = 0; i < 8; i++) {
        int s  = tid + i * 256;
        int m  = s >> 5;
        int k4 = (s & 31) * 4;
        int row = blockRow + m;
        float4 v = make_float4(0.f, 0.f, 0.f, 0.f);
        if (row < M) v = *(const float4*)(A + (size_t)row * FDIM + k4);
        *(float4*)&SA[m * SA_STRIDE + k4] = v;
    }
    __syncthreads();

    float d[2][4][4];
#pragma unroll
    for (int mt = 0; mt < 2; mt++)
#pragma unroll
        for (int nt = 0; nt < 4; nt++)
#pragma unroll
            for (int q = 0; q < 4; q++) d[mt][nt][q] = 0.f;

#pragma unroll 2
    for (int ks = 0; ks < 16; ks++) {
        int k0 = ks * 8;

        unsigned ah[2][4], al[2][4];
#pragma unroll
        for (int mt = 0; mt < 2; mt++) {
            int rb = warpM * 32 + mt * 16;
            float f0 = SA[(rb + g)     * SA_STRIDE + k0 + t];
            float f1 = SA[(rb + g + 8) * SA_STRIDE + k0 + t];
            float f2 = SA[(rb + g)     * SA_STRIDE + k0 + t + 4];
            float f3 = SA[(rb + g + 8) * SA_STRIDE + k0 + t + 4];
            ah[mt][0] = f2tf32(f0); al[mt][0] = f2tf32(f0 - __uint_as_float(ah[mt][0]));
            ah[mt][1] = f2tf32(f1); al[mt][1] = f2tf32(f1 - __uint_as_float(ah[mt][1]));
            ah[mt][2] = f2tf32(f2); al[mt][2] = f2tf32(f2 - __uint_as_float(ah[mt][2]));
            ah[mt][3] = f2tf32(f3); al[mt][3] = f2tf32(f3 - __uint_as_float(ah[mt][3]));
        }

        unsigned bh[4][2], bl[4][2];
#pragma unroll
        for (int nt = 0; nt < 4; nt++) {
            int ng = warpN * 4 + nt;
            float2 vh = __ldg(&WHf[(ks * 16 + ng) * 32 + lane]);
            float2 vl = __ldg(&WLf[(ks * 16 + ng) * 32 + lane]);
            bh[nt][0] = __float_as_uint(vh.x); bh[nt][1] = __float_as_uint(vh.y);
            bl[nt][0] = __float_as_uint(vl.x); bl[nt][1] = __float_as_uint(vl.y);
        }

#pragma unroll
        for (int mt = 0; mt < 2; mt++)
#pragma unroll
            for (int nt = 0; nt < 4; nt++) {
                mma_tf32(d[mt][nt], ah[mt], bh[nt]);
                mma_tf32(d[mt][nt], ah[mt], bl[nt]);
                mma_tf32(d[mt][nt], al[mt], bh[nt]);
            }
    }

#pragma unroll
    for (int mt = 0; mt < 2; mt++) {
        int rbase = blockRow + warpM * 32 + mt * 16 + g;
#pragma unroll
        for (int half = 0; half < 2; half++) {
            int row = rbase + half * 8;
            if (row >= M) continue;
            float dv = g_dinv[row];
#pragma unroll
            for (int nt = 0; nt < 4; nt++) {
                float2 v;
                v.x = d[mt][nt][half * 2 + 0] * dv;
                v.y = d[mt][nt][half * 2 + 1] * dv;
                size_t off = (size_t)row * FDIM + warpN * 32 + nt * 8 + 2 * t;
                *(float2*)(Hs + off) = v;
                *(float2*)(O  + off) = v;
            }
        }
    }
}

// ---------------------------------------------------------------------------
// K9/K11: src-major aggregation. ONE WARP PER SRC NODE:
//   load Hs[src] row once into registers (float4/lane, coalesced 512B),
//   then red.add.v4 it to O[dst] for every outgoing edge.
// No dependent loads in the loop — indices batched via one coalesced load
// + shfl. Atomic writes are the only per-edge traffic.
// ---------------------------------------------------------------------------
__global__ __launch_bounds__(256)
void agg_kernel(int N)
{
    int node = (blockIdx.x * blockDim.x + threadIdx.x) >> 5;
    if (node >= N) return;
    int lane = threadIdx.x & 31;

    int beg = __ldg(&g_off[node]);
    int deg = __ldg(&g_off[node + 1]) - beg;
    if (deg == 0) return;

    float4 v = *(const float4*)(g_Hs + (size_t)node * FDIM + lane * 4);

    for (int base = 0; base < deg; base += 32) {
        int m = deg - base; if (m > 32) m = 32;
        int idx = 0;
        if (lane < m) idx = __ldg(&g_csr[beg + base + lane]);
#pragma unroll 4
        for (int e = 0; e < m; e++) {
            int d = __shfl_sync(0xffffffffu, idx, e);
            red_add_v4(g_O + (size_t)d * FDIM + lane * 4, v);
        }
    }
}

// ---------------------------------------------------------------------------
// K12: layer-1 finalize (in place):  O = relu(O * dinv[row] + b1[col])
// ---------------------------------------------------------------------------
__global__ void finalize_kernel(const float* __restrict__ bias, int N)
{
    int i = blockIdx.x * blockDim.x + threadIdx.x;
    int row = i >> 5;
    if (row >= N) return;
    int c4 = (i & 31) * 4;
    float dv = g_dinv[row];
    float4 v = *(float4*)(g_O + (size_t)row * FDIM + c4);
    float4 b = *(const float4*)(bias + c4);
    v.x = fmaxf(v.x * dv + b.x, 0.f);
    v.y = fmaxf(v.y * dv + b.y, 0.f);
    v.z = fmaxf(v.z * dv + b.z, 0.f);
    v.w = fmaxf(v.w * dv + b.w, 0.f);
    *(float4*)(g_O + (size_t)row * FDIM + c4) = v;
}

// ---------------------------------------------------------------------------
// K13: segment max pool (sorted batch), layer-2 finalize fused
// ---------------------------------------------------------------------------
#define POOL_NODES 256
__global__ void pool_kernel(const int* __restrict__ batch,
                            const float* __restrict__ bias, int M)
{
    int j  = threadIdx.x;
    int n0 = blockIdx.x * POOL_NODES;
    int n1 = min(n0 + POOL_NODES, M);
    if (n0 >= M) return;
    float bj = __ldg(&bias[j]);
    int cur = __ldg(&batch[n0]);
    float m = -3.402823466e38f;
    for (int i = n0; i < n1; i++) {
        int b = __ldg(&batch[i]);
        if (b != cur) {
            atomicMaxFloat(&g_pool[cur * FDIM + j], m);
            cur = b;
            m = -3.402823466e38f;
        }
        float v = g_O[(size_t)i * FDIM + j] * g_dinv[i] + bj;
        m = fmaxf(m, v);
    }
    atomicMaxFloat(&g_pool[cur * FDIM + j], m);
}

// ---------------------------------------------------------------------------
// K14: MLP head, one block per graph (128 threads)
// ---------------------------------------------------------------------------
__global__ void mlp_kernel(const float* __restrict__ Wl1, const float* __restrict__ bl1,
                           const float* __restrict__ Wl2, const float* __restrict__ bl2,
                           const float* __restrict__ Wo,  const float* __restrict__ bo,
                           float* __restrict__ out)
{
    __shared__ float gv[128], t1[128], t2[128], logits[CDIM];
    int g = blockIdx.x, j = threadIdx.x;

    gv[j] = g_pool[g * FDIM + j];
    __syncthreads();

    float acc = bl1[j];
#pragma unroll 8
    for (int k = 0; k < 128; k++) acc += gv[k] * Wl1[k * 128 + j];
    t1[j] = fmaxf(acc, 0.f);
    __syncthreads();

    acc = bl2[j];
#pragma unroll 8
    for (int k = 0; k < 128; k++) acc += t1[k] * Wl2[k * 128 + j];
    t2[j] = fmaxf(acc, 0.f);
    __syncthreads();

    if (j < CDIM) {
        float l = bo[j];
#pragma unroll 8
        for (int k = 0; k < 128; k++) l += t2[k] * Wo[k * CDIM + j];
        logits[j] = l;
    }
    __syncthreads();

    if (j < CDIM) {
        float m = fmaxf(logits[0], logits[1]);
        float e = expf(logits[j] - m);
        float s = expf(logits[0] - m) + expf(logits[1] - m);
        out[g * CDIM + j] = e / s;
    }
}

// ---------------------------------------------------------------------------
// Launch: 0:x 1:edge_index 2:batch 3:W1 4:b1 5:W2 6:b2 7:Wl1 8:bl1 9:Wl2
//         10:bl2 11:Wo 12:bo
// ---------------------------------------------------------------------------
extern "C" void kernel_launch(void* const* d_in, const int* in_sizes, int n_in,
                              void* d_out, int out_size)
{
    const float* x    = (const float*)d_in[0];
    const int*   ei   = (const int*)  d_in[1];
    const int*   batch= (const int*)  d_in[2];
    const float* W1   = (const float*)d_in[3];
    const float* b1   = (const float*)d_in[4];
    const float* W2   = (const float*)d_in[5];
    const float* b2   = (const float*)d_in[6];
    const float* Wl1  = (const float*)d_in[7];
    const float* bl1  = (const float*)d_in[8];
    const float* Wl2  = (const float*)d_in[9];
    const float* bl2  = (const float*)d_in[10];
    const float* Wo   = (const float*)d_in[11];
    const float* bo   = (const float*)d_in[12];
    float* out = (float*)d_out;

    int N = in_sizes[0] / FDIM;        // 50000
    int E = in_sizes[1] / 2;           // 600000
    int G = out_size / CDIM;           // 64
    const int* src = ei;               // edge_index[0]
    const int* dst = ei + E;           // edge_index[1]

    float *Hp, *Op;
    cudaGetSymbolAddress((void**)&Hp, g_Hs);
    cudaGetSymbolAddress((void**)&Op, g_O);

    int initN = (N > G * FDIM) ? N : G * FDIM;
    int nb = (N + 255) / 256;          // 196 scan blocks
    init_kernel<<<(initN + 255) / 256, 256>>>(N, G * FDIM);
    count_kernel<<<(E + 255) / 256, 256>>>(src, dst, E);
    bsum_dinv_kernel<<<nb, 256>>>(N);
    bscan_kernel<<<1, 256>>>(nb);
    fill_kernel<<<nb, 256>>>(N);
    scatter_kernel<<<(E + 255) / 256, 256>>>(src, dst, E);
    wfrag_kernel<<<dim3((WFRAG_ELEMS + 255) / 256, 2), 256>>>(W1, W2);

    int gemm_blocks = (N + 63) / 64;
    int agg_blocks  = (int)(((long long)N * 32 + 255) / 256);
    int fin_blocks  = (int)(((long long)N * 32 + 255) / 256);

    // layer 1: Hs,O = (x@W1)*dinv ; O[dst] += Hs[src] ; O = relu(O*dinv + b1)
    gemm_tc<<<gemm_blocks, 256>>>(x, 0, Hp, Op, N);
    agg_kernel<<<agg_blocks, 256>>>(N);
    finalize_kernel<<<fin_blocks, 256>>>(b1, N);

    // layer 2 (in-place GEMM): Hs,O = (O@W2)*dinv ; O[dst] += Hs[src]
    gemm_tc<<<gemm_blocks, 256>>>(Op, 1, Hp, Op, N);
    agg_kernel<<<agg_blocks, 256>>>(N);

    pool_kernel<<<(N + POOL_NODES - 1) / POOL_NODES, 128>>>(batch, b2, N);
    mlp_kernel<<<G, 128>>>(Wl1, bl1, Wl2, bl2, Wo, bo, out);
}